// round 7
// baseline (speedup 1.0000x reference)
#include <cuda_runtime.h>
#include <math.h>
#include <stdint.h>

// Problem constants
#define B_    2
#define T_    2048
#define H_    1024
#define NH_   16
#define HD_   64
#define WIN_  256

// Scratch (device globals — allocation-free per harness rules)
__device__ float g_qkv[(size_t)B_ * T_ * 3 * H_];   // [B,T,3H]
__device__ float g_att[(size_t)B_ * T_ * H_];       // [B,T,H] attention output

__device__ __forceinline__ float f2tf32(float x) {
    uint32_t u;
    asm("cvt.rna.tf32.f32 %0, %1;" : "=r"(u) : "f"(x));
    return __uint_as_float(u);
}

__device__ __forceinline__ uint32_t ld_tf32(const float* p) {
    uint32_t u;
    asm("cvt.rna.tf32.f32 %0, %1;" : "=r"(u) : "f"(*p));
    return u;
}

__device__ __forceinline__ void mma_tf32(float c[4], const uint32_t a[4], const uint32_t b[2]) {
    asm volatile(
        "mma.sync.aligned.m16n8k8.row.col.f32.tf32.tf32.f32 "
        "{%0,%1,%2,%3}, {%4,%5,%6,%7}, {%8,%9}, {%0,%1,%2,%3};"
        : "+f"(c[0]), "+f"(c[1]), "+f"(c[2]), "+f"(c[3])
        : "r"(a[0]), "r"(a[1]), "r"(a[2]), "r"(a[3]), "r"(b[0]), "r"(b[1]));
}

__device__ __forceinline__ void cp_async16(float* smem_dst, const float* gsrc) {
    uint32_t s = (uint32_t)__cvta_generic_to_shared(smem_dst);
    asm volatile("cp.async.cg.shared.global [%0], [%1], 16;" :: "r"(s), "l"(gsrc));
}
__device__ __forceinline__ void cp_commit() {
    asm volatile("cp.async.commit_group;");
}
template <int N>
__device__ __forceinline__ void cp_wait() {
    asm volatile("cp.async.wait_group %0;" :: "n"(N));
}

// ---------------------------------------------------------------------------
// TF32 tensor-core GEMM with cp.async double buffering.
// C[M,N] = A[M,K] @ Bm[K,N] + bias[N]
// 128x128 block tile, BK=32, 256 threads = 8 warps (2x4), warp tile 64x32.
// Raw fp32 staged in smem via LDGSTS; tf32 cvt applied at fragment load.
// A stride 36, B stride 136 (conflict-free fragment access).
// ---------------------------------------------------------------------------
#define BM 128
#define BN 128
#define BK 32
#define AS_STRIDE 36
#define BS_STRIDE 136
#define STAGE_FLOATS (BM * AS_STRIDE + BK * BS_STRIDE)   // 4608 + 4352 = 8960
#define GEMM_SMEM (2 * STAGE_FLOATS * 4)                 // 71680 B

__global__ __launch_bounds__(256, 2)
void gemm_tf32_bias(const float* __restrict__ A, const float* __restrict__ Bm,
                    const float* __restrict__ bias, float* __restrict__ C,
                    int M, int N, int K)
{
    extern __shared__ float smem[];
    // stage s: As = smem + s*STAGE_FLOATS, Bs = As + BM*AS_STRIDE

    const int tid  = threadIdx.x;
    const int wid  = tid >> 5;
    const int lane = tid & 31;
    const int wm   = wid >> 2;          // 0..1 (M dir)
    const int wn   = wid & 3;           // 0..3 (N dir)
    const int grp  = lane >> 2;         // 0..7
    const int qid  = lane & 3;          // 0..3

    const float* Ab = A  + (size_t)(blockIdx.y * BM) * K;
    const float* Bb = Bm + (size_t)(blockIdx.x * BN);

    // per-thread copy coordinates
    const int aRow0 = tid >> 3;          // row for i-th A float4: aRow0 + i*? -- we use flat
    float acc[4][4][4];
#pragma unroll
    for (int m = 0; m < 4; m++)
#pragma unroll
        for (int n = 0; n < 4; n++)
#pragma unroll
            for (int r = 0; r < 4; r++) acc[m][n][r] = 0.f;

    const int ITER = K / BK;

    // ---- stage loader ----
    auto load_stage = [&](int k0, int s) {
        float* As = smem + s * STAGE_FLOATS;
        float* Bs = As + BM * AS_STRIDE;
#pragma unroll
        for (int i = 0; i < 4; i++) {
            const int flat = tid + i * 256;          // 0..1023
            const int r  = flat >> 3;                // 0..127
            const int c4 = (flat & 7) * 4;           // 0..28
            cp_async16(As + r * AS_STRIDE + c4, Ab + (size_t)r * K + k0 + c4);
        }
#pragma unroll
        for (int i = 0; i < 4; i++) {
            const int flat = tid + i * 256;
            const int r  = flat >> 5;                // 0..31
            const int c4 = (flat & 31) * 4;          // 0..124
            cp_async16(Bs + r * BS_STRIDE + c4, Bb + (size_t)(k0 + r) * N + c4);
        }
        cp_commit();
    };
    (void)aRow0;

    load_stage(0, 0);

    for (int it = 0; it < ITER; it++) {
        if (it + 1 < ITER) {
            load_stage((it + 1) * BK, (it + 1) & 1);
            cp_wait<1>();
        } else {
            cp_wait<0>();
        }
        __syncthreads();

        const float* As = smem + (it & 1) * STAGE_FLOATS;
        const float* Bs = As + BM * AS_STRIDE;

#pragma unroll
        for (int ks = 0; ks < BK / 8; ks++) {
            const int kb = ks * 8;
            uint32_t af[4][4], bf[4][2];
#pragma unroll
            for (int m = 0; m < 4; m++) {
                const int r = wm * 64 + m * 16;
                af[m][0] = ld_tf32(As + (r + grp    ) * AS_STRIDE + kb + qid    );
                af[m][1] = ld_tf32(As + (r + grp + 8) * AS_STRIDE + kb + qid    );
                af[m][2] = ld_tf32(As + (r + grp    ) * AS_STRIDE + kb + qid + 4);
                af[m][3] = ld_tf32(As + (r + grp + 8) * AS_STRIDE + kb + qid + 4);
            }
#pragma unroll
            for (int n = 0; n < 4; n++) {
                const int c = wn * 32 + n * 8 + grp;
                bf[n][0] = ld_tf32(Bs + (kb + qid    ) * BS_STRIDE + c);
                bf[n][1] = ld_tf32(Bs + (kb + qid + 4) * BS_STRIDE + c);
            }
#pragma unroll
            for (int m = 0; m < 4; m++)
#pragma unroll
                for (int n = 0; n < 4; n++)
                    mma_tf32(acc[m][n], af[m], bf[n]);
        }
        __syncthreads();   // all reads done before stage (it+2)&1 == (it&1) overwrite
    }

    // Epilogue with bias
#pragma unroll
    for (int m = 0; m < 4; m++) {
        const int row0 = blockIdx.y * BM + wm * 64 + m * 16 + grp;
#pragma unroll
        for (int n = 0; n < 4; n++) {
            const int col = blockIdx.x * BN + wn * 32 + n * 8 + qid * 2;
            const float b0 = bias[col], b1 = bias[col + 1];
            float2 v0 = make_float2(acc[m][n][0] + b0, acc[m][n][1] + b1);
            float2 v1 = make_float2(acc[m][n][2] + b0, acc[m][n][3] + b1);
            *(float2*)(C + (size_t)row0 * N + col)       = v0;
            *(float2*)(C + (size_t)(row0 + 8) * N + col) = v1;
        }
    }
}

// ---------------------------------------------------------------------------
// Banded causal attention on tensor cores (tf32 mma, flash online softmax).
// Unchanged from R3 (58us, passing).
// ---------------------------------------------------------------------------
#define ATTN_SMEM2 ((64*68*3 + 64*72) * 4)

__global__ __launch_bounds__(128)
void attn_mma_kernel(float* __restrict__ out)
{
    extern __shared__ float sm[];
    float* Qs = sm;                   // [64][68]
    float* Ps = Qs + 64 * 68;         // [64][68]
    float* Ks = Ps + 64 * 68;         // [64][68]
    float* Vs = Ks + 64 * 68;         // [64][72]

    const int qt  = blockIdx.x;
    const int h   = blockIdx.y;
    const int b   = blockIdx.z;
    const int tid = threadIdx.x;
    const int wid  = tid >> 5;
    const int lane = tid & 31;
    const int g = lane >> 2;
    const int q = lane & 3;
    const int r0 = wid * 16;

    const size_t rs = 3 * H_;
    const size_t base_bt = (size_t)b * T_ * rs + (size_t)h * HD_;
    const size_t qbase = base_bt + (size_t)(qt * 64) * rs;

#pragma unroll
    for (int it = 0; it < 8; it++) {
        const int idx = tid + it * 128;
        const int i = idx >> 4, d4 = (idx & 15) << 2;
        float4 v = *(const float4*)&g_qkv[qbase + (size_t)i * rs + d4];
        float4 w;
        w.x = f2tf32(v.x * 0.125f);
        w.y = f2tf32(v.y * 0.125f);
        w.z = f2tf32(v.z * 0.125f);
        w.w = f2tf32(v.w * 0.125f);
        *(float4*)&Qs[i * 68 + d4] = w;
    }

    float oc[8][4];
#pragma unroll
    for (int nt = 0; nt < 8; nt++)
#pragma unroll
        for (int r = 0; r < 4; r++) oc[nt][r] = 0.f;

    float m0 = -1e30f, m1 = -1e30f, l0 = 0.f, l1 = 0.f;

    int kt0 = qt - 4; if (kt0 < 0) kt0 = 0;

    for (int kt = kt0; kt <= qt; kt++) {
        __syncthreads();

        const size_t kbase = base_bt + (size_t)(kt * 64) * rs + H_;
#pragma unroll
        for (int it = 0; it < 8; it++) {
            const int idx = tid + it * 128;
            const int j = idx >> 4, d4 = (idx & 15) << 2;
            float4 kv = *(const float4*)&g_qkv[kbase + (size_t)j * rs + d4];
            float4 vv = *(const float4*)&g_qkv[kbase + H_ + (size_t)j * rs + d4];
            float4 kw, vw;
            kw.x = f2tf32(kv.x); kw.y = f2tf32(kv.y); kw.z = f2tf32(kv.z); kw.w = f2tf32(kv.w);
            vw.x = f2tf32(vv.x); vw.y = f2tf32(vv.y); vw.z = f2tf32(vv.z); vw.w = f2tf32(vv.w);
            *(float4*)&Ks[j * 68 + d4] = kw;
            *(float4*)&Vs[j * 72 + d4] = vw;
        }
        __syncthreads();

        float s[8][4];
#pragma unroll
        for (int nt = 0; nt < 8; nt++)
#pragma unroll
            for (int r = 0; r < 4; r++) s[nt][r] = 0.f;

#pragma unroll
        for (int ks = 0; ks < 8; ks++) {
            const int kb = ks * 8;
            uint32_t a[4];
            a[0] = __float_as_uint(Qs[(r0 + g    ) * 68 + kb + q    ]);
            a[1] = __float_as_uint(Qs[(r0 + g + 8) * 68 + kb + q    ]);
            a[2] = __float_as_uint(Qs[(r0 + g    ) * 68 + kb + q + 4]);
            a[3] = __float_as_uint(Qs[(r0 + g + 8) * 68 + kb + q + 4]);
#pragma unroll
            for (int nt = 0; nt < 8; nt++) {
                uint32_t bb[2];
                bb[0] = __float_as_uint(Ks[(nt * 8 + g) * 68 + kb + q    ]);
                bb[1] = __float_as_uint(Ks[(nt * 8 + g) * 68 + kb + q + 4]);
                mma_tf32(s[nt], a, bb);
            }
        }

        const int ig0 = qt * 64 + r0 + g;
        const int ig1 = ig0 + 8;
#pragma unroll
        for (int nt = 0; nt < 8; nt++) {
            const int jg = kt * 64 + nt * 8 + 2 * q;
            int d00 = ig0 - jg;     if (d00 < 0 || d00 >= WIN_) s[nt][0] = -1e30f;
            int d01 = ig0 - jg - 1; if (d01 < 0 || d01 >= WIN_) s[nt][1] = -1e30f;
            int d10 = ig1 - jg;     if (d10 < 0 || d10 >= WIN_) s[nt][2] = -1e30f;
            int d11 = ig1 - jg - 1; if (d11 < 0 || d11 >= WIN_) s[nt][3] = -1e30f;
        }
        float mx0 = -1e30f, mx1 = -1e30f;
#pragma unroll
        for (int nt = 0; nt < 8; nt++) {
            mx0 = fmaxf(mx0, fmaxf(s[nt][0], s[nt][1]));
            mx1 = fmaxf(mx1, fmaxf(s[nt][2], s[nt][3]));
        }
        mx0 = fmaxf(mx0, __shfl_xor_sync(0xffffffffu, mx0, 1));
        mx0 = fmaxf(mx0, __shfl_xor_sync(0xffffffffu, mx0, 2));
        mx1 = fmaxf(mx1, __shfl_xor_sync(0xffffffffu, mx1, 1));
        mx1 = fmaxf(mx1, __shfl_xor_sync(0xffffffffu, mx1, 2));

        const float mn0 = fmaxf(m0, mx0), mn1 = fmaxf(m1, mx1);
        const float e0 = __expf(m0 - mn0), e1 = __expf(m1 - mn1);
        float rs0 = 0.f, rs1 = 0.f;
#pragma unroll
        for (int nt = 0; nt < 8; nt++) {
            const float p00 = __expf(s[nt][0] - mn0);
            const float p01 = __expf(s[nt][1] - mn0);
            const float p10 = __expf(s[nt][2] - mn1);
            const float p11 = __expf(s[nt][3] - mn1);
            rs0 += p00 + p01;
            rs1 += p10 + p11;
            float2 v0 = make_float2(f2tf32(p00), f2tf32(p01));
            float2 v1 = make_float2(f2tf32(p10), f2tf32(p11));
            *(float2*)&Ps[(r0 + g    ) * 68 + nt * 8 + 2 * q] = v0;
            *(float2*)&Ps[(r0 + g + 8) * 68 + nt * 8 + 2 * q] = v1;
        }
        rs0 += __shfl_xor_sync(0xffffffffu, rs0, 1);
        rs0 += __shfl_xor_sync(0xffffffffu, rs0, 2);
        rs1 += __shfl_xor_sync(0xffffffffu, rs1, 1);
        rs1 += __shfl_xor_sync(0xffffffffu, rs1, 2);

        l0 = l0 * e0 + rs0;  m0 = mn0;
        l1 = l1 * e1 + rs1;  m1 = mn1;

#pragma unroll
        for (int nt = 0; nt < 8; nt++) {
            oc[nt][0] *= e0; oc[nt][1] *= e0;
            oc[nt][2] *= e1; oc[nt][3] *= e1;
        }
        __syncthreads();

#pragma unroll
        for (int ks = 0; ks < 8; ks++) {
            const int kb = ks * 8;
            uint32_t a[4];
            a[0] = __float_as_uint(Ps[(r0 + g    ) * 68 + kb + q    ]);
            a[1] = __float_as_uint(Ps[(r0 + g + 8) * 68 + kb + q    ]);
            a[2] = __float_as_uint(Ps[(r0 + g    ) * 68 + kb + q + 4]);
            a[3] = __float_as_uint(Ps[(r0 + g + 8) * 68 + kb + q + 4]);
#pragma unroll
            for (int nt = 0; nt < 8; nt++) {
                uint32_t bb[2];
                bb[0] = __float_as_uint(Vs[(kb + q    ) * 72 + nt * 8 + g]);
                bb[1] = __float_as_uint(Vs[(kb + q + 4) * 72 + nt * 8 + g]);
                mma_tf32(oc[nt], a, bb);
            }
        }
    }

    const float inv0 = 1.f / l0, inv1 = 1.f / l1;
    const int row0g = qt * 64 + r0 + g;
#pragma unroll
    for (int nt = 0; nt < 8; nt++) {
        const int col = h * HD_ + nt * 8 + 2 * q;
        float2 v0 = make_float2(oc[nt][0] * inv0, oc[nt][1] * inv0);
        float2 v1 = make_float2(oc[nt][2] * inv1, oc[nt][3] * inv1);
        *(float2*)&out[(size_t)(b * T_ + row0g    ) * H_ + col] = v0;
        *(float2*)&out[(size_t)(b * T_ + row0g + 8) * H_ + col] = v1;
    }
}

// ---------------------------------------------------------------------------
// Launch: qkv GEMM -> banded attention (mma) -> out GEMM
// ---------------------------------------------------------------------------
extern "C" void kernel_launch(void* const* d_in, const int* in_sizes, int n_in,
                              void* d_out, int out_size)
{
    const float* x     = (const float*)d_in[0];
    const float* W_qkv = (const float*)d_in[1];
    const float* b_qkv = (const float*)d_in[2];
    const float* W_out = (const float*)d_in[3];
    const float* b_out = (const float*)d_in[4];
    float* out = (float*)d_out;

    float* qkv; cudaGetSymbolAddress((void**)&qkv, g_qkv);
    float* att; cudaGetSymbolAddress((void**)&att, g_att);

    const int M = B_ * T_;

    cudaFuncSetAttribute(gemm_tf32_bias,
                         cudaFuncAttributeMaxDynamicSharedMemorySize, GEMM_SMEM);
    {
        dim3 grid((3 * H_) / BN, M / BM);
        gemm_tf32_bias<<<grid, 256, GEMM_SMEM>>>(x, W_qkv, b_qkv, qkv, M, 3 * H_, H_);
    }
    {
        cudaFuncSetAttribute(attn_mma_kernel,
                             cudaFuncAttributeMaxDynamicSharedMemorySize, ATTN_SMEM2);
        dim3 grid(T_ / 64, NH_, B_);
        attn_mma_kernel<<<grid, 128, ATTN_SMEM2>>>(att);
    }
    {
        dim3 grid(H_ / BN, M / BM);
        gemm_tf32_bias<<<grid, 256, GEMM_SMEM>>>(att, W_out, b_out, out, M, H_, H_);
    }
}